// round 15
// baseline (speedup 1.0000x reference)
#include <cuda_runtime.h>
#include <cuda_bf16.h>

#define WIN    11
#define HALO   5
#define TILE_H 32
#define NT     64        // thread t owns 4 columns inside a 256-col strip
#define STRIPW 256
#define IMW    512
#define IMH    512

// Horizontal 11-tap sums of (x, y, x^2, y^2, x*y) for 4 consecutive columns,
// accumulated (ADD) or subtracted (!ADD) into the vertical accumulators.
// Needed taps: cols [c0-5, c0+8] = 14 floats per image, loaded exactly:
// scalar(c0-5) + float4(c0-4) + float4(c0) + float4(c0+4) + scalar(c0+8).
template<bool ADD>
__device__ __forceinline__ void hsums_acc(const float* __restrict__ ra,
                                          const float* __restrict__ rb,
                                          int c0,
                                          float* __restrict__ ax,  float* __restrict__ ay,
                                          float* __restrict__ axx, float* __restrict__ ayy,
                                          float* __restrict__ axy)
{
    const int c_m5 = c0 - 5, c_m4 = c0 - 4, c_p4 = c0 + 4, c_p8 = c0 + 8;

    float af[14], bf[14];

    af[0]  = ((unsigned)c_m5 < IMW) ? ra[c_m5] : 0.f;
    bf[0]  = ((unsigned)c_m5 < IMW) ? rb[c_m5] : 0.f;
    af[13] = ((unsigned)c_p8 < IMW) ? ra[c_p8] : 0.f;
    bf[13] = ((unsigned)c_p8 < IMW) ? rb[c_p8] : 0.f;

    {
        float4 va = make_float4(0.f,0.f,0.f,0.f), vb = va;
        if ((unsigned)c_m4 < IMW) { va = *(const float4*)(ra + c_m4); vb = *(const float4*)(rb + c_m4); }
        af[1]=va.x; af[2]=va.y; af[3]=va.z; af[4]=va.w;
        bf[1]=vb.x; bf[2]=vb.y; bf[3]=vb.z; bf[4]=vb.w;
    }
    {
        // c0 is always in [0, IMW) by construction
        float4 va = *(const float4*)(ra + c0);
        float4 vb = *(const float4*)(rb + c0);
        af[5]=va.x; af[6]=va.y; af[7]=va.z; af[8]=va.w;
        bf[5]=vb.x; bf[6]=vb.y; bf[7]=vb.z; bf[8]=vb.w;
    }
    {
        float4 va = make_float4(0.f,0.f,0.f,0.f), vb = va;
        if ((unsigned)c_p4 < IMW) { va = *(const float4*)(ra + c_p4); vb = *(const float4*)(rb + c_p4); }
        af[9]=va.x;  af[10]=va.y; af[11]=va.z; af[12]=va.w;
        bf[9]=vb.x;  bf[10]=vb.y; bf[11]=vb.z; bf[12]=vb.w;
    }

    // initial 11-tap window for column c0 (taps af[0..10])
    float sx=0.f, sy=0.f, sxx=0.f, syy=0.f, sxy=0.f;
    #pragma unroll
    for (int j = 0; j < 11; ++j) {
        const float a = af[j], c = bf[j];
        sx += a; sy += c;
        sxx = fmaf(a, a, sxx);
        syy = fmaf(c, c, syy);
        sxy = fmaf(a, c, sxy);
    }
    if (ADD) { ax[0]+=sx; ay[0]+=sy; axx[0]+=sxx; ayy[0]+=syy; axy[0]+=sxy; }
    else     { ax[0]-=sx; ay[0]-=sy; axx[0]-=sxx; ayy[0]-=syy; axy[0]-=sxy; }

    // slide to columns c0+1..c0+3 (enter af[10+s], leave af[s-1])
    #pragma unroll
    for (int s = 1; s < 4; ++s) {
        const float ai = af[10+s], ao = af[s-1];
        const float bi = bf[10+s], bo = bf[s-1];
        sx += ai - ao;
        sy += bi - bo;
        sxx = fmaf(ai, ai, sxx);  sxx = fmaf(-ao, ao, sxx);
        syy = fmaf(bi, bi, syy);  syy = fmaf(-bo, bo, syy);
        sxy = fmaf(ai, bi, sxy);  sxy = fmaf(-ao, bo, sxy);
        if (ADD) { ax[s]+=sx; ay[s]+=sy; axx[s]+=sxx; ayy[s]+=syy; axy[s]+=sxy; }
        else     { ax[s]-=sx; ay[s]-=sy; axx[s]-=sxx; ayy[s]-=syy; axy[s]-=sxy; }
    }
}

// No smem, no barriers. Vertical sliding window; leaving row's horizontal
// sums recomputed from a re-read 11 rows back. CTA = 256-col strip x 32 rows:
// re-read window 11x256x2x4B = 22.5KB/CTA -> stays L1-resident even at
// ~14 CTAs/SM, and vertical halo overhead is 42/32 = 1.31x.
__global__ __launch_bounds__(NT) void ssim_kernel(
    const float* __restrict__ img,
    const float* __restrict__ ref,
    const float* __restrict__ drange,
    float* __restrict__ out)
{
    const int t       = threadIdx.x;
    const int b       = blockIdx.x >> 1;
    const int strip   = blockIdx.x & 1;
    const int rowBase = blockIdx.y * TILE_H;
    const int c0      = strip * STRIPW + 4 * t;

    const float dr    = drange[b];
    // Raw (un-normalized) window sums; fold 121^2 into the constants.
    const float c1    = (0.01f * dr) * (0.01f * dr) * 14641.0f;
    const float c2    = (0.03f * dr) * (0.03f * dr) * 14641.0f;
    const float covn  = 121.0f / 120.0f;
    const float covn2 = 2.0f * covn;

    const size_t base = (size_t)b * IMW * IMH;
    const float* pa = img + base + (long)(rowBase - HALO) * IMW;   // incoming row
    const float* pb = ref + base + (long)(rowBase - HALO) * IMW;
    float*       ro = out + base + (size_t)rowBase * IMW + c0;

    float ax[4], ay[4], axx[4], ayy[4], axy[4];
    #pragma unroll
    for (int c = 0; c < 4; ++c) { ax[c]=0.f; ay[c]=0.f; axx[c]=0.f; ayy[c]=0.f; axy[c]=0.f; }

    for (int i = 0; i < TILE_H + 2 * HALO; ++i) {
        const int gy = rowBase - HALO + i;

        // ---- add incoming row ----
        if ((unsigned)gy < (unsigned)IMH)
            hsums_acc<true>(pa, pb, c0, ax, ay, axx, ayy, axy);

        // ---- subtract leaving row (added 11 iterations ago), recomputed ----
        const int gys = gy - WIN;
        if (i >= WIN && (unsigned)gys < (unsigned)IMH)
            hsums_acc<false>(pa - WIN * IMW, pb - WIN * IMW, c0, ax, ay, axx, ayy, axy);

        pa += IMW; pb += IMW;

        // ---- emit output row once 11-row window is complete ----
        if (i >= 2 * HALO) {
            float rr[4];
            #pragma unroll
            for (int c = 0; c < 4; ++c) {
                const float Sx = ax[c],  Sy = ay[c];
                const float Sxx = axx[c], Syy = ayy[c], Sxy = axy[c];
                const float p  = Sx * Sy;
                const float xx = Sx * Sx;
                const float yy = Sy * Sy;
                const float A1 = fmaf(2.0f, p, c1);
                const float B1 = xx + yy + c1;
                const float A2 = fmaf(covn2, fmaf(121.0f, Sxy, -p), c2);
                const float vx = fmaf(121.0f, Sxx, -xx);
                const float vy = fmaf(121.0f, Syy, -yy);
                const float B2 = fmaf(covn, vx + vy, c2);
                rr[c] = __fdividef(A1 * A2, B1 * B2);
            }
            *(float4*)ro = make_float4(rr[0], rr[1], rr[2], rr[3]);
            ro += IMW;
        }
    }
}

extern "C" void kernel_launch(void* const* d_in, const int* in_sizes, int n_in,
                              void* d_out, int out_size) {
    const float* img = (const float*)d_in[0];
    const float* ref = (const float*)d_in[1];
    const float* dr  = (const float*)d_in[2];
    float* out = (float*)d_out;

    const int B = in_sizes[2];   // 64

    // (B * 2 strips, 16 y-tiles) = 2048 CTAs x 2 warps
    dim3 grid(B * 2, IMH / TILE_H, 1);
    ssim_kernel<<<grid, NT>>>(img, ref, dr, out);
}